// round 14
// baseline (speedup 1.0000x reference)
#include <cuda_runtime.h>
#include <cstdint>

#define NTASKS 64
#define NROWS  2048
#define INSZ   512
#define OUTSZ  512
#define MT     64          // M rows per CTA tile
#define NTILE  128         // N cols per CTA
#define KT     8           // K per stage tile
#define NSTAGE 12
#define BATCH  4
#define THREADS 256
#define MAXROWS 256

// SMEM strides (floats), conflict-free for LDSM(A)/scalar(B)
#define AS 12              // 8 k + 4 pad  (48B row stride: 3r mod 8 lanes, conflict-free)
#define BS 136             // 128 n + 8 pad (8*t4 + g8 covers 32 banks)
#define A_BYTES (MT * AS * 4)             // 3072
#define STAGE   (A_BYTES + KT * BS * 4)   // 3072 + 4352 = 7424
#define SMEM_TOTAL (NSTAGE * STAGE)       // 89088 -> 2 CTAs/SM

// ---------------- helpers ----------------
__device__ __forceinline__ uint32_t smem_u32(const void* p) {
    uint32_t a;
    asm("{ .reg .u64 t; cvta.to.shared.u64 t, %1; cvt.u32.u64 %0, t; }" : "=r"(a) : "l"(p));
    return a;
}
__device__ __forceinline__ void cpa16(uint32_t dst, const void* src, int nbytes) {
    asm volatile("cp.async.cg.shared.global [%0], [%1], 16, %2;"
                 :: "r"(dst), "l"(src), "r"(nbytes) : "memory");
}
__device__ __forceinline__ void cp_commit() {
    asm volatile("cp.async.commit_group;" ::: "memory");
}
template <int N>
__device__ __forceinline__ void cp_wait() {
    asm volatile("cp.async.wait_group %0;" :: "n"(N) : "memory");
}
__device__ __forceinline__ uint32_t lds32(uint32_t a) {
    uint32_t v;
    asm volatile("ld.shared.b32 %0, [%1];" : "=r"(v) : "r"(a));
    return v;
}
__device__ __forceinline__ void ldm_x4(uint32_t* r, uint32_t a) {
    asm volatile("ldmatrix.sync.aligned.m8n8.x4.shared.b16 {%0,%1,%2,%3}, [%4];"
                 : "=r"(r[0]), "=r"(r[1]), "=r"(r[2]), "=r"(r[3]) : "r"(a));
}
__device__ __forceinline__ void mma16888(float* c, const uint32_t* a, const uint32_t* b) {
    asm volatile("mma.sync.aligned.m16n8k8.row.col.f32.tf32.tf32.f32 "
                 "{%0,%1,%2,%3}, {%4,%5,%6,%7}, {%8,%9}, {%0,%1,%2,%3};"
                 : "+f"(c[0]), "+f"(c[1]), "+f"(c[2]), "+f"(c[3])
                 : "r"(a[0]), "r"(a[1]), "r"(a[2]), "r"(a[3]), "r"(b[0]), "r"(b[1]));
}

// ---------------------------------------------------------------------------
// Fused kernel: per-CTA row gather + tf32 GEMM (raw fp32 bits as tf32 / RZ).
// grid = (4, 64), 256 threads (8 warps, 2m x 4n, warp tile 32m x 32n),
// 2 CTAs/SM. 12-stage cp.async pipeline, KT=8, 4 tiles per barrier, depth 8.
// ---------------------------------------------------------------------------
__global__ __launch_bounds__(THREADS, 2)
void task_gemm_fused(const float* __restrict__ X, const void* __restrict__ ids_raw,
                     const float* __restrict__ W, float* __restrict__ Out) {
    extern __shared__ __align__(16) char smem[];
    const uint32_t sb = smem_u32(smem);
    __shared__ int s_rows[MAXROWS];
    __shared__ int s_wsum[8], s_woff[8];
    __shared__ int s_cnt;

    const int t    = blockIdx.y;
    const int col0 = blockIdx.x * NTILE;
    const int tid = threadIdx.x, lane = tid & 31, wid = tid >> 5;

    // ---- width detection: int64 ids have all odd 32-bit words zero ----
    const int* ids32 = (const int*)ids_raw;
    int odd = 0;
    #pragma unroll
    for (int j = 0; j < 4; j++) odd |= ids32[2 * (tid * 4 + j) + 1];
    const int wide = !__syncthreads_or(odd);

    // ---- gather this task's rows (stable, ascending); 8 rows per thread ----
    int myrows[8];
    int c = 0;
    #pragma unroll
    for (int j = 0; j < 8; j++) {
        const int r = tid * 8 + j;
        const int id = wide ? ids32[2 * r] : ids32[r];
        if (id == t) myrows[c++] = r;
    }
    int pre = c;
    #pragma unroll
    for (int d = 1; d < 32; d <<= 1) {
        int v = __shfl_up_sync(0xFFFFFFFF, pre, d);
        if (lane >= d) pre += v;
    }
    if (lane == 31) s_wsum[wid] = pre;
    __syncthreads();
    if (tid == 0) {
        int s = 0;
        #pragma unroll
        for (int i = 0; i < 8; i++) { s_woff[i] = s; s += s_wsum[i]; }
        s_cnt = s;
    }
    __syncthreads();
    {
        const int off = s_woff[wid] + pre - c;
        for (int k = 0; k < c; k++)
            if (off + k < MAXROWS) s_rows[off + k] = myrows[k];
    }
    __syncthreads();
    const int cnt = min(s_cnt, MAXROWS);
    if (cnt == 0) return;

    // producer roles: A uses tid<128 (64 rows x 2 chunks); B all 256 (8 rows x 32)
    const int am = tid >> 1;          // A row 0..127 (only <64 used)
    const int aq = tid & 1;           // A 16B chunk in row
    const int bm = tid >> 5;          // B k-row 0..7
    const int bq = lane;              // B 16B chunk in row

    const float* __restrict__ Wt = W + (size_t)t * INSZ * OUTSZ + col0;

    // consumer roles: 8 warps = 2m x 4n, warp tile 32m x 32n
    const int m0w = (wid & 1) * 32;
    const int n0w = (wid >> 1) * 32;
    const int g8  = lane >> 2;
    const int t4  = lane & 3;
    const int mrow = m0w + ((lane >> 3) & 1) * 8 + (lane & 7);
    const int kadd = (lane >> 4) * 4;

    const int NKT = INSZ / KT;   // 64

    for (int base = 0; base < cnt; base += MT) {
        const int nrows = min(MT, cnt - base);
        const bool aload = am < MT;
        const int asz = (aload && am < nrows) ? 16 : 0;
        const float* __restrict__ aptr =
            (aload && am < nrows) ? (X + (size_t)s_rows[base + am] * INSZ + aq * 4) : X;
        const bool mactive = m0w < nrows;   // warp-uniform padding skip

        auto issue = [&](int kt) {
            const uint32_t stg = sb + (kt % NSTAGE) * STAGE;
            if (aload)
                cpa16(stg + (am * AS + aq * 4) * 4, aptr + kt * KT, asz);
            cpa16(stg + A_BYTES + (bm * BS + bq * 4) * 4,
                  Wt + (size_t)(kt * KT + bm) * OUTSZ + bq * 4, 16);
            cp_commit();
        };

        float acc[2][4][4];
        #pragma unroll
        for (int i = 0; i < 2; i++)
            #pragma unroll
            for (int j = 0; j < 4; j++)
                #pragma unroll
                for (int p = 0; p < 4; p++) acc[i][j][p] = 0.f;

        #pragma unroll
        for (int k = 0; k < 2 * BATCH; k++) issue(k);   // prefill 8 tiles

        auto compute_tile = [&](int kt) {
            const uint32_t stg = sb + (kt % NSTAGE) * STAGE;
            const uint32_t abase = stg + (mrow * AS + kadd) * 4;
            const uint32_t bbase = stg + A_BYTES + (t4 * BS + n0w + g8) * 4;
            uint32_t af[2][4], bf[4][2];
            #pragma unroll
            for (int mt = 0; mt < 2; mt++)
                ldm_x4(af[mt], abase + mt * 16 * AS * 4);
            #pragma unroll
            for (int nf = 0; nf < 4; nf++) {
                const uint32_t r = bbase + nf * 32;
                bf[nf][0] = lds32(r);
                bf[nf][1] = lds32(r + 4 * BS * 4);
            }
            #pragma unroll
            for (int mt = 0; mt < 2; mt++)
                #pragma unroll
                for (int nf = 0; nf < 4; nf++)
                    mma16888(acc[mt][nf], af[mt], bf[nf]);
        };

        for (int kb = 0; kb < NKT; kb += BATCH) {
            cp_wait<BATCH>();          // tiles kb..kb+3 resident (4 groups out)
            __syncthreads();
            #pragma unroll
            for (int j = 0; j < BATCH; j++) {
                if (kb + 2 * BATCH + j < NKT) issue(kb + 2 * BATCH + j);
                else                          cp_commit();
            }
            if (mactive) {
                #pragma unroll
                for (int j = 0; j < BATCH; j++) compute_tile(kb + j);
            }
        }

        // epilogue: C frag m16n8: {c0,c1}@(g8, 2*t4), {c2,c3}@(g8+8, 2*t4)
        #pragma unroll
        for (int mt = 0; mt < 2; mt++) {
            const int ml0 = m0w + mt * 16 + g8;
            const int ml1 = ml0 + 8;
            const int o0 = (ml0 < nrows) ? s_rows[base + ml0] : -1;
            const int o1 = (ml1 < nrows) ? s_rows[base + ml1] : -1;
            #pragma unroll
            for (int nf = 0; nf < 4; nf++) {
                const int col = col0 + n0w + nf * 8 + t4 * 2;
                if (o0 >= 0)
                    *(float2*)(Out + (size_t)o0 * OUTSZ + col) =
                        make_float2(acc[mt][nf][0], acc[mt][nf][1]);
                if (o1 >= 0)
                    *(float2*)(Out + (size_t)o1 * OUTSZ + col) =
                        make_float2(acc[mt][nf][2], acc[mt][nf][3]);
            }
        }
        __syncthreads();
    }
}

extern "C" void kernel_launch(void* const* d_in, const int* in_sizes, int n_in,
                              void* d_out, int out_size) {
    const float* X        = (const float*)d_in[0];   // [2048, 512] fp32
    const void*  task_ids = d_in[1];                 // [2048] int64 (or int32)
    const float* W        = (const float*)d_in[2];   // [64, 512, 512] fp32
    float*       Out      = (float*)d_out;           // [2048, 512] fp32

    cudaFuncSetAttribute(task_gemm_fused, cudaFuncAttributeMaxDynamicSharedMemorySize, SMEM_TOTAL);
    dim3 grid(OUTSZ / NTILE, NTASKS);
    task_gemm_fused<<<grid, THREADS, SMEM_TOTAL>>>(X, task_ids, W, Out);
}

// round 15
// speedup vs baseline: 1.0089x; 1.0089x over previous
#include <cuda_runtime.h>
#include <cstdint>

#define NTASKS 64
#define NROWS  2048
#define INSZ   512
#define OUTSZ  512
#define MT     64          // M rows per CTA tile
#define NTILE  128         // N cols per CTA
#define KT     16          // K per stage tile
#define NSTAGE 8
#define THREADS 256
#define MAXROWS 256

// SMEM strides (floats), conflict-free for LDSM(A)/scalar(B)
#define AS 20              // 16 k + 4 pad
#define BS 136             // 128 n + 8 pad
#define A_BYTES (MT * AS * 4)             // 5120
#define STAGE   (A_BYTES + KT * BS * 4)   // 13824
#define SMEM_TOTAL (NSTAGE * STAGE)       // 110592 -> 2 CTAs/SM

// ---------------- helpers ----------------
__device__ __forceinline__ uint32_t smem_u32(const void* p) {
    uint32_t a;
    asm("{ .reg .u64 t; cvta.to.shared.u64 t, %1; cvt.u32.u64 %0, t; }" : "=r"(a) : "l"(p));
    return a;
}
__device__ __forceinline__ void cpa16(uint32_t dst, const void* src, int nbytes) {
    asm volatile("cp.async.cg.shared.global [%0], [%1], 16, %2;"
                 :: "r"(dst), "l"(src), "r"(nbytes) : "memory");
}
__device__ __forceinline__ void cp_commit() {
    asm volatile("cp.async.commit_group;" ::: "memory");
}
template <int N>
__device__ __forceinline__ void cp_wait() {
    asm volatile("cp.async.wait_group %0;" :: "n"(N) : "memory");
}
__device__ __forceinline__ uint32_t lds32(uint32_t a) {
    uint32_t v;
    asm volatile("ld.shared.b32 %0, [%1];" : "=r"(v) : "r"(a));
    return v;
}
__device__ __forceinline__ void ldm_x4(uint32_t* r, uint32_t a) {
    asm volatile("ldmatrix.sync.aligned.m8n8.x4.shared.b16 {%0,%1,%2,%3}, [%4];"
                 : "=r"(r[0]), "=r"(r[1]), "=r"(r[2]), "=r"(r[3]) : "r"(a));
}
__device__ __forceinline__ void mma16888(float* c, const uint32_t* a, const uint32_t* b) {
    asm volatile("mma.sync.aligned.m16n8k8.row.col.f32.tf32.tf32.f32 "
                 "{%0,%1,%2,%3}, {%4,%5,%6,%7}, {%8,%9}, {%0,%1,%2,%3};"
                 : "+f"(c[0]), "+f"(c[1]), "+f"(c[2]), "+f"(c[3])
                 : "r"(a[0]), "r"(a[1]), "r"(a[2]), "r"(a[3]), "r"(b[0]), "r"(b[1]));
}

// ---------------------------------------------------------------------------
// Fused kernel: B-first prefill -> overlapped row gather -> tf32 GEMM.
// grid = (4, 64), 256 threads (8 warps, 2m x 4n), 2 CTAs/SM.
// 8-stage cp.async pipeline (7 deep), KT=16. Raw fp32 bits as tf32 (RZ).
// ---------------------------------------------------------------------------
__global__ __launch_bounds__(THREADS, 2)
void task_gemm_fused(const float* __restrict__ X, const void* __restrict__ ids_raw,
                     const float* __restrict__ W, float* __restrict__ Out) {
    extern __shared__ __align__(16) char smem[];
    const uint32_t sb = smem_u32(smem);
    __shared__ int s_rows[MAXROWS];
    __shared__ int s_wsum[8], s_woff[8];
    __shared__ int s_cnt;

    const int t    = blockIdx.y;
    const int col0 = blockIdx.x * NTILE;
    const int tid = threadIdx.x, lane = tid & 31, wid = tid >> 5;

    // producer roles
    const int am = tid >> 2;          // A row 0..63
    const int aq = tid & 3;           // A 16B chunk in row
    const int bm = tid >> 4;          // B k-row 0..15
    const int bq = tid & 15;          // B 8-float group

    const float* __restrict__ Wt = W + (size_t)t * INSZ * OUTSZ + col0;

    // ---- B-only prefill for tiles 0..6: no dependence on task ids ----
    auto issue_b = [&](int kt) {
        const uint32_t stg = sb + (kt & (NSTAGE - 1)) * STAGE;
        const float* bsrc = Wt + (size_t)(kt * KT + bm) * OUTSZ + bq * 8;
        const uint32_t bo = stg + A_BYTES + (bm * BS + bq * 8) * 4;
        cpa16(bo,      bsrc,     16);
        cpa16(bo + 16, bsrc + 4, 16);
        cp_commit();
    };
    #pragma unroll
    for (int k = 0; k < NSTAGE - 1; k++) issue_b(k);

    // ---- width detection (reads only first 8KB: safe for int32 too) ----
    const int* ids32 = (const int*)ids_raw;
    int odd = 0;
    #pragma unroll
    for (int j = 0; j < 4; j++) odd |= ids32[2 * (tid * 4 + j) + 1];
    const int wide = !__syncthreads_or(odd);

    // ---- gather this task's rows (stable, ascending) ----
    int myrows[8];
    int c = 0;
    #pragma unroll
    for (int j = 0; j < 8; j++) {
        const int r = tid * 8 + j;
        const int id = wide ? ids32[2 * r] : ids32[r];
        if (id == t) myrows[c++] = r;
    }
    int pre = c;
    #pragma unroll
    for (int d = 1; d < 32; d <<= 1) {
        int v = __shfl_up_sync(0xFFFFFFFF, pre, d);
        if (lane >= d) pre += v;
    }
    if (lane == 31) s_wsum[wid] = pre;
    __syncthreads();
    if (tid == 0) {
        int s = 0;
        #pragma unroll
        for (int i = 0; i < 8; i++) { s_woff[i] = s; s += s_wsum[i]; }
        s_cnt = s;
    }
    __syncthreads();
    {
        const int off = s_woff[wid] + pre - c;
        for (int k = 0; k < c; k++)
            if (off + k < MAXROWS) s_rows[off + k] = myrows[k];
    }
    __syncthreads();
    const int cnt = min(s_cnt, MAXROWS);
    if (cnt == 0) { cp_wait<0>(); return; }

    // consumer roles: 8 warps = 2m x 4n, warp tile 32m x 32n
    const int m0w = (wid & 1) * 32;
    const int n0w = (wid >> 1) * 32;
    const int g8  = lane >> 2;
    const int t4  = lane & 3;
    const int mrow = m0w + ((lane >> 3) & 1) * 8 + (lane & 7);
    const int kadd = (lane >> 4) * 4;

    const int NKT = INSZ / KT;   // 32

    for (int base = 0; base < cnt; base += MT) {
        const int nrows = min(MT, cnt - base);
        const bool avalid = am < nrows;
        const int asz = avalid ? 16 : 0;
        const float* __restrict__ aptr =
            avalid ? (X + (size_t)s_rows[base + am] * INSZ + aq * 4) : X;

        auto issue = [&](int kt) {   // full A+B issue
            const uint32_t stg = sb + (kt & (NSTAGE - 1)) * STAGE;
            cpa16(stg + (am * AS + aq * 4) * 4, aptr + kt * KT, asz);
            const float* bsrc = Wt + (size_t)(kt * KT + bm) * OUTSZ + bq * 8;
            const uint32_t bo = stg + A_BYTES + (bm * BS + bq * 8) * 4;
            cpa16(bo,      bsrc,     16);
            cpa16(bo + 16, bsrc + 4, 16);
            cp_commit();
        };

        if (base == 0) {
            // A-halves of stages 0..6 via plain LDG -> STS (B already in flight)
            #pragma unroll
            for (int k = 0; k < NSTAGE - 1; k++) {
                const uint32_t ao = sb + (k & (NSTAGE - 1)) * STAGE
                                  + (am * AS + aq * 4) * 4;
                float4 v = avalid ? *(const float4*)(aptr + k * KT)
                                  : make_float4(0.f, 0.f, 0.f, 0.f);
                *(float4*)(smem + (ao - sb)) = v;
            }
        } else {
            #pragma unroll
            for (int k = 0; k < NSTAGE - 1; k++) issue(k);
        }

        float acc[2][4][4];
        #pragma unroll
        for (int i = 0; i < 2; i++)
            #pragma unroll
            for (int j = 0; j < 4; j++)
                #pragma unroll
                for (int p = 0; p < 4; p++) acc[i][j][p] = 0.f;

        for (int kt = 0; kt < NKT; kt++) {
            cp_wait<NSTAGE - 2>();     // oldest tile's group complete
            __syncthreads();           // also orders the STS A-preload (base==0)
            if (kt + NSTAGE - 1 < NKT) issue(kt + NSTAGE - 1);
            else                       cp_commit();      // keep group count uniform

            const uint32_t stg = sb + (kt & (NSTAGE - 1)) * STAGE;
            const uint32_t abase = stg + (mrow * AS + kadd) * 4;
            const uint32_t bbase = stg + A_BYTES + (t4 * BS + n0w + g8) * 4;

            uint32_t af[2][2][4], bf[2][4][2];
            #pragma unroll
            for (int ks = 0; ks < 2; ks++) {
                const int k0 = ks * 8;
                #pragma unroll
                for (int mt = 0; mt < 2; mt++)
                    ldm_x4(af[ks][mt], abase + (mt * 16 * AS + k0) * 4);
                #pragma unroll
                for (int nf = 0; nf < 4; nf++) {
                    const uint32_t r = bbase + (k0 * BS + nf * 8) * 4;
                    bf[ks][nf][0] = lds32(r);
                    bf[ks][nf][1] = lds32(r + 4 * BS * 4);
                }
            }
            #pragma unroll
            for (int ks = 0; ks < 2; ks++)
                #pragma unroll
                for (int mt = 0; mt < 2; mt++)
                    #pragma unroll
                    for (int nf = 0; nf < 4; nf++)
                        mma16888(acc[mt][nf], af[ks][mt], bf[ks][nf]);
        }

        // epilogue: C frag m16n8: {c0,c1}@(g8, 2*t4), {c2,c3}@(g8+8, 2*t4)
        #pragma unroll
        for (int mt = 0; mt < 2; mt++) {
            const int ml0 = m0w + mt * 16 + g8;
            const int ml1 = ml0 + 8;
            const int o0 = (ml0 < nrows) ? s_rows[base + ml0] : -1;
            const int o1 = (ml1 < nrows) ? s_rows[base + ml1] : -1;
            #pragma unroll
            for (int nf = 0; nf < 4; nf++) {
                const int col = col0 + n0w + nf * 8 + t4 * 2;
                if (o0 >= 0)
                    *(float2*)(Out + (size_t)o0 * OUTSZ + col) =
                        make_float2(acc[mt][nf][0], acc[mt][nf][1]);
                if (o1 >= 0)
                    *(float2*)(Out + (size_t)o1 * OUTSZ + col) =
                        make_float2(acc[mt][nf][2], acc[mt][nf][3]);
            }
        }
        __syncthreads();
    }
}

extern "C" void kernel_launch(void* const* d_in, const int* in_sizes, int n_in,
                              void* d_out, int out_size) {
    const float* X        = (const float*)d_in[0];   // [2048, 512] fp32
    const void*  task_ids = d_in[1];                 // [2048] int64 (or int32)
    const float* W        = (const float*)d_in[2];   // [64, 512, 512] fp32
    float*       Out      = (float*)d_out;           // [2048, 512] fp32

    cudaFuncSetAttribute(task_gemm_fused, cudaFuncAttributeMaxDynamicSharedMemorySize, SMEM_TOTAL);
    dim3 grid(OUTSZ / NTILE, NTASKS);
    task_gemm_fused<<<grid, THREADS, SMEM_TOTAL>>>(X, task_ids, W, Out);
}

// round 16
// speedup vs baseline: 1.1635x; 1.1533x over previous
#include <cuda_runtime.h>
#include <cstdint>

#define NTASKS 64
#define NROWS  2048
#define INSZ   512
#define OUTSZ  512
#define MT     64          // M rows per CTA tile
#define NTILE  128         // N cols per CTA
#define KT     16          // K per stage tile
#define NSTAGE 8
#define THREADS 256
#define MAXROWS 256

// SMEM strides (floats), conflict-free for LDSM(A)/scalar(B)
#define AS 20              // 16 k + 4 pad
#define BS 136             // 128 n + 8 pad
#define A_BYTES (MT * AS * 4)             // 5120
#define STAGE   (A_BYTES + KT * BS * 4)   // 13824
#define SMEM_TOTAL (NSTAGE * STAGE)       // 110592 -> 2 CTAs/SM

// ---------------- helpers ----------------
__device__ __forceinline__ uint32_t smem_u32(const void* p) {
    uint32_t a;
    asm("{ .reg .u64 t; cvta.to.shared.u64 t, %1; cvt.u32.u64 %0, t; }" : "=r"(a) : "l"(p));
    return a;
}
__device__ __forceinline__ void cpa16(uint32_t dst, const void* src, int nbytes) {
    asm volatile("cp.async.cg.shared.global [%0], [%1], 16, %2;"
                 :: "r"(dst), "l"(src), "r"(nbytes) : "memory");
}
__device__ __forceinline__ void cpa_arrive(uint32_t mbar) {
    asm volatile("cp.async.mbarrier.arrive.noinc.shared.b64 [%0];" :: "r"(mbar) : "memory");
}
__device__ __forceinline__ void mbar_init(uint32_t a, uint32_t cnt) {
    asm volatile("mbarrier.init.shared.b64 [%0], %1;" :: "r"(a), "r"(cnt) : "memory");
}
__device__ __forceinline__ void mbar_arrive(uint32_t a) {
    asm volatile("mbarrier.arrive.shared.b64 _, [%0];" :: "r"(a) : "memory");
}
__device__ __forceinline__ void mbar_wait(uint32_t a, uint32_t parity) {
    uint32_t done;
    asm volatile("{ .reg .pred p; mbarrier.try_wait.parity.acquire.cta.shared::cta.b64 p, [%1], %2;"
                 " selp.b32 %0, 1, 0, p; }" : "=r"(done) : "r"(a), "r"(parity) : "memory");
    if (!done) {
        asm volatile("{ .reg .pred P1; WL_%=:"
                     " mbarrier.try_wait.parity.acquire.cta.shared::cta.b64 P1, [%0], %1, 0x989680;"
                     " @P1 bra.uni WD_%=; bra.uni WL_%=; WD_%=: }"
                     :: "r"(a), "r"(parity) : "memory");
    }
}
__device__ __forceinline__ uint32_t lds32(uint32_t a) {
    uint32_t v;
    asm volatile("ld.shared.b32 %0, [%1];" : "=r"(v) : "r"(a));
    return v;
}
__device__ __forceinline__ void ldm_x4(uint32_t* r, uint32_t a) {
    asm volatile("ldmatrix.sync.aligned.m8n8.x4.shared.b16 {%0,%1,%2,%3}, [%4];"
                 : "=r"(r[0]), "=r"(r[1]), "=r"(r[2]), "=r"(r[3]) : "r"(a));
}
__device__ __forceinline__ void mma16888(float* c, const uint32_t* a, const uint32_t* b) {
    asm volatile("mma.sync.aligned.m16n8k8.row.col.f32.tf32.tf32.f32 "
                 "{%0,%1,%2,%3}, {%4,%5,%6,%7}, {%8,%9}, {%0,%1,%2,%3};"
                 : "+f"(c[0]), "+f"(c[1]), "+f"(c[2]), "+f"(c[3])
                 : "r"(a[0]), "r"(a[1]), "r"(a[2]), "r"(a[3]), "r"(b[0]), "r"(b[1]));
}

// ---------------------------------------------------------------------------
// Fused kernel: per-CTA row gather + tf32 GEMM (raw fp32 bits as tf32 / RZ).
// grid = (4, 64), 256 threads (8 warps, 2m x 4n), 2 CTAs/SM.
// 8-stage cp.async pipeline gated by per-stage full/empty mbarriers:
// warps drift up to 7 tiles instead of converging at a block barrier per tile.
// ---------------------------------------------------------------------------
__global__ __launch_bounds__(THREADS, 2)
void task_gemm_fused(const float* __restrict__ X, const void* __restrict__ ids_raw,
                     const float* __restrict__ W, float* __restrict__ Out) {
    extern __shared__ __align__(16) char smem[];
    const uint32_t sb = smem_u32(smem);
    __shared__ __align__(8) unsigned long long s_full[NSTAGE], s_empty[NSTAGE];
    __shared__ int s_rows[MAXROWS];
    __shared__ int s_wsum[8], s_woff[8];
    __shared__ int s_cnt;

    const int t    = blockIdx.y;
    const int col0 = blockIdx.x * NTILE;
    const int tid = threadIdx.x, lane = tid & 31, wid = tid >> 5;
    const uint32_t fullb  = smem_u32(s_full);
    const uint32_t emptyb = smem_u32(s_empty);

    if (tid < NSTAGE)     mbar_init(fullb  + tid * 8, THREADS);
    else if (tid < 2 * NSTAGE) mbar_init(emptyb + (tid - NSTAGE) * 8, THREADS);

    // ---- width detection: int64 ids have all odd 32-bit words zero ----
    const int* ids32 = (const int*)ids_raw;
    int odd = 0;
    #pragma unroll
    for (int j = 0; j < 4; j++) odd |= ids32[2 * (tid * 4 + j) + 1];
    const int wide = !__syncthreads_or(odd);   // also publishes mbarrier inits

    // ---- gather this task's rows (stable, ascending) ----
    int myrows[8];
    int c = 0;
    #pragma unroll
    for (int j = 0; j < 8; j++) {
        const int r = tid * 8 + j;
        const int id = wide ? ids32[2 * r] : ids32[r];
        if (id == t) myrows[c++] = r;
    }
    int pre = c;
    #pragma unroll
    for (int d = 1; d < 32; d <<= 1) {
        int v = __shfl_up_sync(0xFFFFFFFF, pre, d);
        if (lane >= d) pre += v;
    }
    if (lane == 31) s_wsum[wid] = pre;
    __syncthreads();
    if (tid == 0) {
        int s = 0;
        #pragma unroll
        for (int i = 0; i < 8; i++) { s_woff[i] = s; s += s_wsum[i]; }
        s_cnt = s;
    }
    __syncthreads();
    {
        const int off = s_woff[wid] + pre - c;
        for (int k = 0; k < c; k++)
            if (off + k < MAXROWS) s_rows[off + k] = myrows[k];
    }
    __syncthreads();
    const int cnt = min(s_cnt, MAXROWS);
    if (cnt == 0) return;

    // producer roles
    const int am = tid >> 2;          // A row 0..63
    const int aq = tid & 3;           // A 16B chunk in row
    const int bm = tid >> 4;          // B k-row 0..15
    const int bq = tid & 15;          // B 8-float group

    const float* __restrict__ Wt = W + (size_t)t * INSZ * OUTSZ + col0;

    // consumer roles: 8 warps = 2m x 4n, warp tile 32m x 32n
    const int m0w = (wid & 1) * 32;
    const int n0w = (wid >> 1) * 32;
    const int g8  = lane >> 2;
    const int t4  = lane & 3;
    const int mrow = m0w + ((lane >> 3) & 1) * 8 + (lane & 7);
    const int kadd = (lane >> 4) * 4;

    const int NKT = INSZ / KT;   // 32
    int gtb = 0;                 // global tile counter base (pipeline phase state)

    for (int base = 0; base < cnt; base += MT) {
        const int nrows = min(MT, cnt - base);
        const bool avalid = am < nrows;
        const int asz = avalid ? 16 : 0;
        const float* __restrict__ aptr =
            avalid ? (X + (size_t)s_rows[base + am] * INSZ + aq * 4) : X;

        // fill tile (global index gt, chunk-local kt). Stage = gt & 7, fill f = gt >> 3.
        auto issue = [&](int gt, int kt) {
            const int s = gt & (NSTAGE - 1);
            const int f = gt >> 3;
            if (f > 0) mbar_wait(emptyb + s * 8, (f - 1) & 1);   // fill f-1 fully read
            const uint32_t stg = sb + s * STAGE;
            cpa16(stg + (am * AS + aq * 4) * 4, aptr + kt * KT, asz);
            const float* bsrc = Wt + (size_t)(kt * KT + bm) * OUTSZ + bq * 8;
            const uint32_t bo = stg + A_BYTES + (bm * BS + bq * 8) * 4;
            cpa16(bo,      bsrc,     16);
            cpa16(bo + 16, bsrc + 4, 16);
            cpa_arrive(fullb + s * 8);   // arrive on full[s] when these land
        };

        float acc[2][4][4];
        #pragma unroll
        for (int i = 0; i < 2; i++)
            #pragma unroll
            for (int j = 0; j < 4; j++)
                #pragma unroll
                for (int p = 0; p < 4; p++) acc[i][j][p] = 0.f;

        #pragma unroll
        for (int k = 0; k < NSTAGE - 1; k++) issue(gtb + k, k);   // 7 tiles in flight

        for (int kt = 0; kt < NKT; kt++) {
            if (kt + NSTAGE - 1 < NKT) issue(gtb + kt + NSTAGE - 1, kt + NSTAGE - 1);

            const int gt = gtb + kt;
            const int s  = gt & (NSTAGE - 1);
            mbar_wait(fullb + s * 8, (gt >> 3) & 1);   // stage resident (acquire)

            const uint32_t stg = sb + s * STAGE;
            const uint32_t abase = stg + (mrow * AS + kadd) * 4;
            const uint32_t bbase = stg + A_BYTES + (t4 * BS + n0w + g8) * 4;

            uint32_t af[2][2][4], bf[2][4][2];
            #pragma unroll
            for (int ks = 0; ks < 2; ks++) {
                const int k0 = ks * 8;
                #pragma unroll
                for (int mt = 0; mt < 2; mt++)
                    ldm_x4(af[ks][mt], abase + (mt * 16 * AS + k0) * 4);
                #pragma unroll
                for (int nf = 0; nf < 4; nf++) {
                    const uint32_t r = bbase + (k0 * BS + nf * 8) * 4;
                    bf[ks][nf][0] = lds32(r);
                    bf[ks][nf][1] = lds32(r + 4 * BS * 4);
                }
            }
            #pragma unroll
            for (int ks = 0; ks < 2; ks++)
                #pragma unroll
                for (int mt = 0; mt < 2; mt++)
                    #pragma unroll
                    for (int nf = 0; nf < 4; nf++)
                        mma16888(acc[mt][nf], af[ks][mt], bf[ks][nf]);

            mbar_arrive(emptyb + s * 8);   // done reading this fill
        }
        gtb += NKT;

        // epilogue: C frag m16n8: {c0,c1}@(g8, 2*t4), {c2,c3}@(g8+8, 2*t4)
        #pragma unroll
        for (int mt = 0; mt < 2; mt++) {
            const int ml0 = m0w + mt * 16 + g8;
            const int ml1 = ml0 + 8;
            const int o0 = (ml0 < nrows) ? s_rows[base + ml0] : -1;
            const int o1 = (ml1 < nrows) ? s_rows[base + ml1] : -1;
            #pragma unroll
            for (int nf = 0; nf < 4; nf++) {
                const int col = col0 + n0w + nf * 8 + t4 * 2;
                if (o0 >= 0)
                    *(float2*)(Out + (size_t)o0 * OUTSZ + col) =
                        make_float2(acc[mt][nf][0], acc[mt][nf][1]);
                if (o1 >= 0)
                    *(float2*)(Out + (size_t)o1 * OUTSZ + col) =
                        make_float2(acc[mt][nf][2], acc[mt][nf][3]);
            }
        }
    }
}

extern "C" void kernel_launch(void* const* d_in, const int* in_sizes, int n_in,
                              void* d_out, int out_size) {
    const float* X        = (const float*)d_in[0];   // [2048, 512] fp32
    const void*  task_ids = d_in[1];                 // [2048] int64 (or int32)
    const float* W        = (const float*)d_in[2];   // [64, 512, 512] fp32
    float*       Out      = (float*)d_out;           // [2048, 512] fp32

    cudaFuncSetAttribute(task_gemm_fused, cudaFuncAttributeMaxDynamicSharedMemorySize, SMEM_TOTAL);
    dim3 grid(OUTSZ / NTILE, NTASKS);
    task_gemm_fused<<<grid, THREADS, SMEM_TOTAL>>>(X, task_ids, W, Out);
}